// round 14
// baseline (speedup 1.0000x reference)
#include <cuda_runtime.h>
#include <cuda_fp16.h>
#include <cstdint>

#define SQ 2048
#define EM 2048
#define NH 32
#define HD 64

// ---------------- device scratch (allocation-free rule) ----------------------
__device__ float g_Q[NH * SQ * HD];
__device__ float g_K[NH * SQ * HD];
__device__ float g_V[NH * SQ * HD];
__device__ float g_scores[(size_t)NH * SQ * SQ];   // fallback only

__device__ __half g_hidH[SQ * EM], g_hidL[SQ * EM];
__device__ __half g_WqH[EM * EM],  g_WqL[EM * EM];
__device__ __half g_WkH[EM * EM],  g_WkL[EM * EM];
__device__ __half g_WvH[EM * EM],  g_WvL[EM * EM];
__device__ __half g_WoH[EM * EM],  g_WoL[EM * EM];
__device__ __half g_ctxH[SQ * EM], g_ctxL[SQ * EM];
// shaped [h][s][hd] hi/lo splits written by projection epilogues
__device__ __half g_QsH[NH * SQ * HD], g_QsL[NH * SQ * HD];
__device__ __half g_KsH[NH * SQ * HD], g_KsL[NH * SQ * HD];
__device__ __half g_VsH[NH * SQ * HD], g_VsL[NH * SQ * HD];
// fp16 hi/lo of normalized attention weights (causal 128-tiles only)
__device__ __half g_AwH[(size_t)NH * SQ * SQ];
__device__ __half g_AwL[(size_t)NH * SQ * SQ];

// ---------------- helpers ----------------------------------------------------
__device__ __forceinline__ uint32_t smem_u32(const void* p) {
    uint32_t a;
    asm("{ .reg .u64 t; cvta.to.shared.u64 t, %1; cvt.u32.u64 %0, t; }"
        : "=r"(a) : "l"(p));
    return a;
}
__device__ __forceinline__ void ldsm4(uint32_t* r, uint32_t addr) {
    asm volatile("ldmatrix.sync.aligned.m8n8.x4.shared.b16 {%0,%1,%2,%3}, [%4];"
                 : "=r"(r[0]), "=r"(r[1]), "=r"(r[2]), "=r"(r[3]) : "r"(addr));
}
__device__ __forceinline__ void ldsm4t(uint32_t* r, uint32_t addr) {
    asm volatile("ldmatrix.sync.aligned.m8n8.x4.trans.shared.b16 {%0,%1,%2,%3}, [%4];"
                 : "=r"(r[0]), "=r"(r[1]), "=r"(r[2]), "=r"(r[3]) : "r"(addr));
}
__device__ __forceinline__ void mma16816(float* c, const uint32_t* a,
                                         const uint32_t* b) {
    asm volatile(
        "mma.sync.aligned.m16n8k16.row.col.f32.f16.f16.f32 "
        "{%0,%1,%2,%3}, {%4,%5,%6,%7}, {%8,%9}, {%0,%1,%2,%3};"
        : "+f"(c[0]), "+f"(c[1]), "+f"(c[2]), "+f"(c[3])
        : "r"(a[0]), "r"(a[1]), "r"(a[2]), "r"(a[3]), "r"(b[0]), "r"(b[1]));
}
__device__ __forceinline__ uint32_t sw(uint32_t off) {
    return off ^ ((off >> 3) & 0x70);
}

// fp32 -> fp16 hi/lo split for all 5 matrices in ONE launch (grid.y selects)
__global__ void __launch_bounds__(256)
split_f16_all(const float* __restrict__ x0, const float* __restrict__ x1,
              const float* __restrict__ x2, const float* __restrict__ x3,
              const float* __restrict__ x4,
              __half* __restrict__ h0, __half* __restrict__ l0,
              __half* __restrict__ h1, __half* __restrict__ l1,
              __half* __restrict__ h2, __half* __restrict__ l2,
              __half* __restrict__ h3, __half* __restrict__ l3,
              __half* __restrict__ h4, __half* __restrict__ l4, int n)
{
    const int z = blockIdx.y;
    const float* x = (z == 0) ? x0 : (z == 1) ? x1 : (z == 2) ? x2
                   : (z == 3) ? x3 : x4;
    __half* hi = (z == 0) ? h0 : (z == 1) ? h1 : (z == 2) ? h2
               : (z == 3) ? h3 : h4;
    __half* lo = (z == 0) ? l0 : (z == 1) ? l1 : (z == 2) ? l2
               : (z == 3) ? l3 : l4;
    const int stride = gridDim.x * 256 * 4;
    for (int i = (blockIdx.x * 256 + threadIdx.x) * 4; i < n; i += stride) {
        float4 v = *(const float4*)(x + i);
        __half h[4], l[4];
        float vv[4] = {v.x, v.y, v.z, v.w};
#pragma unroll
        for (int j = 0; j < 4; j++) {
            h[j] = __float2half_rn(vv[j]);
            l[j] = __float2half_rn(vv[j] - __half2float(h[j]));
        }
        *(uint2*)(hi + i) = *(const uint2*)h;
        *(uint2*)(lo + i) = *(const uint2*)l;
    }
}

// ============================================================================
// MMA stage over operand tiles (Ah,Al,Bh[,Bl]), 128 rows x 128B each.
// NPROD==3: AhBh + AhBl + AlBh.  NPROD==2: AhBh + AlBh (Bl never touched).
// ============================================================================
#define TILE_B 16384

template <int NPROD>
__device__ __forceinline__ void
mma_stage(uint32_t base, int wm, int wn, int l, float acc[4][4][4])
{
    const uint32_t aH = base, aL = base + TILE_B;
    const uint32_t bH = base + 2 * TILE_B, bL = base + 3 * TILE_B;
#pragma unroll
    for (int ks = 0; ks < 4; ks++) {
        uint32_t ah[4][4], al[4][4], bh[4][2], bl[4][2];
#pragma unroll
        for (int mt = 0; mt < 4; mt++) {
            int row = wm * 64 + mt * 16 + (l & 15);
            int chk = ks * 2 + (l >> 4);
            uint32_t off = sw(row * 128 + chk * 16);
            ldsm4(ah[mt], aH + off);
            ldsm4(al[mt], aL + off);
        }
#pragma unroll
        for (int j = 0; j < 2; j++) {
            int row = wn * 32 + j * 16 + (l & 7) + ((l >> 4) << 3);
            int chk = ks * 2 + ((l >> 3) & 1);
            uint32_t off = sw(row * 128 + chk * 16);
            uint32_t t4[4];
            ldsm4(t4, bH + off);
            bh[2 * j][0] = t4[0]; bh[2 * j][1] = t4[1];
            bh[2 * j + 1][0] = t4[2]; bh[2 * j + 1][1] = t4[3];
            if (NPROD == 3) {
                ldsm4(t4, bL + off);
                bl[2 * j][0] = t4[0]; bl[2 * j][1] = t4[1];
                bl[2 * j + 1][0] = t4[2]; bl[2 * j + 1][1] = t4[3];
            }
        }
#pragma unroll
        for (int mt = 0; mt < 4; mt++)
#pragma unroll
            for (int nt = 0; nt < 4; nt++) {
                mma16816(acc[mt][nt], ah[mt], bh[nt]);
                if (NPROD == 3) mma16816(acc[mt][nt], ah[mt], bl[nt]);
                mma16816(acc[mt][nt], al[mt], bh[nt]);
            }
    }
}

// ============================================================================
// GEMM body: 3-stage cp.async ring, ONE __syncthreads per stage.
// iter i: wait(stage i landed) -> sync (publishes data + frees buf (i-1)%3)
//         -> issue stage i+2 into buf (i+2)%3 == (i-1)%3 -> mma(buf i%3)
// ============================================================================
#define SMEM_SZ (12 * TILE_B)   // 3 stages x 4 tiles x 16KB = 196608

template <int NPROD, int MODE, bool SPLIT>
__device__ __forceinline__ void
gemm_body(const __half* Ah, const __half* Al,
          const __half* Bh, const __half* Bl,
          const float* bias, float* C, __half* Chi, __half* Clo,
          float scale, int m0, int n0, uint32_t sb, int tid)
{
    const int w = tid >> 5, l = tid & 31;
    const int wm = w >> 2, wn = w & 3;

    auto issue = [&](int s, int k0) {
#pragma unroll
        for (int it = 0; it < 16; it++) {
            if (NPROD == 2 && it >= 12) continue;   // skip Bl tile
            int c = tid + it * 256;
            int o = c >> 10;
            int row = (c >> 3) & 127;
            int chk = c & 7;
            const __half* p = (o == 0) ? Ah : (o == 1) ? Al
                             : (o == 2) ? Bh : Bl;
            int rb = (o < 2) ? m0 : n0;
            const void* g = p + (size_t)(rb + row) * 2048 + k0 + chk * 8;
            uint32_t d = sb + (uint32_t)(s * 4 + o) * TILE_B
                         + sw(row * 128 + chk * 16);
            asm volatile("cp.async.cg.shared.global [%0], [%1], 16;\n"
                         :: "r"(d), "l"(g));
        }
        asm volatile("cp.async.commit_group;\n" ::: "memory");
    };

    float acc[4][4][4] = {};
    issue(0, 0);
    issue(1, 64);

    const int NS = 2048 / 64;
    for (int i = 0; i < NS; i++) {
        if (i == NS - 1)
            asm volatile("cp.async.wait_group 0;\n" ::: "memory");
        else
            asm volatile("cp.async.wait_group 1;\n" ::: "memory");
        __syncthreads();
        if (i + 2 < NS) issue((i + 2) % 3, (i + 2) * 64);
        mma_stage<NPROD>(sb + (uint32_t)((i % 3) * 4) * TILE_B, wm, wn, l, acc);
    }
    __syncthreads();   // protect smem before epilogue (none needed) / exit

#pragma unroll
    for (int mt = 0; mt < 4; mt++) {
#pragma unroll
        for (int nt = 0; nt < 4; nt++) {
            int m = m0 + wm * 64 + mt * 16 + (l >> 2);
            int n = n0 + wn * 32 + nt * 8 + (l & 3) * 2;
#pragma unroll
            for (int hf = 0; hf < 2; hf++) {
                int row = m + hf * 8;
                float v0 = (acc[mt][nt][hf * 2 + 0] + bias[n]) * scale;
                float v1 = (acc[mt][nt][hf * 2 + 1] + bias[n + 1]) * scale;
                size_t idx;
                if (MODE == 0)
                    idx = (size_t)row * 2048 + n;
                else
                    idx = (((size_t)(n >> 6)) * SQ + row) * HD + (n & 63);
                C[idx] = v0;
                C[idx + 1] = v1;
                if (SPLIT) {
                    __half h0 = __float2half_rn(v0);
                    __half h1 = __float2half_rn(v1);
                    __half l0 = __float2half_rn(v0 - __half2float(h0));
                    __half l1 = __float2half_rn(v1 - __half2float(h1));
                    Chi[idx] = h0; Chi[idx + 1] = h1;
                    Clo[idx] = l0; Clo[idx + 1] = l1;
                }
            }
        }
    }
}

// Merged Q/K/V projection, grid (16,16,3); compile-time dispatch per z.
__global__ void __launch_bounds__(256)
qkv_gemm(const __half* __restrict__ hH, const __half* __restrict__ hL,
         const __half* __restrict__ WqH, const __half* __restrict__ WqL,
         const __half* __restrict__ WkH, const __half* __restrict__ WkL,
         const __half* __restrict__ WvH,
         const float* __restrict__ bq, const float* __restrict__ bk,
         const float* __restrict__ bv,
         float* __restrict__ gq, float* __restrict__ gk, float* __restrict__ gv,
         __half* __restrict__ QsH, __half* __restrict__ QsL,
         __half* __restrict__ KsH, __half* __restrict__ KsL,
         __half* __restrict__ VsH, __half* __restrict__ VsL)
{
    extern __shared__ char smem[];
    const uint32_t sb = smem_u32(smem);
    const int tid = threadIdx.x;
    const int m0 = blockIdx.y * 128, n0 = blockIdx.x * 128;
    const int z = blockIdx.z;
    if (z == 0)
        gemm_body<3, 1, true>(hH, hL, WqH, WqL, bq, gq, QsH, QsL,
                              0.125f, m0, n0, sb, tid);
    else if (z == 1)
        gemm_body<3, 1, true>(hH, hL, WkH, WkL, bk, gk, KsH, KsL,
                              1.0f, m0, n0, sb, tid);
    else
        gemm_body<2, 1, true>(hH, hL, WvH, WvH, bv, gv, VsH, VsL,
                              1.0f, m0, n0, sb, tid);
}

// Out-projection: 2-product, plain row-major output.
__global__ void __launch_bounds__(256)
out_gemm(const __half* __restrict__ cH, const __half* __restrict__ cL,
         const __half* __restrict__ WoH,
         const float* __restrict__ bo, float* __restrict__ out)
{
    extern __shared__ char smem[];
    gemm_body<2, 0, false>(cH, cL, WoH, WoH, bo, out, nullptr, nullptr, 1.0f,
                           blockIdx.y * 128, blockIdx.x * 128,
                           smem_u32(smem), threadIdx.x);
}

// ============================================================================
// Tensor-core scores: scores[h] = Qs @ Ks^T per head, K=64 (one stage).
// Above-diagonal tiles: pure zero-fill (these are the final weight zeros).
// ============================================================================
#define SC_SMEM (4 * TILE_B)

__global__ void __launch_bounds__(256)
scores_mma(const __half* __restrict__ Qh, const __half* __restrict__ Ql,
           const __half* __restrict__ Kh, const __half* __restrict__ Kl,
           float* __restrict__ scores)
{
    const int h  = blockIdx.z;
    const int q0 = blockIdx.y * 128;
    const int k0 = blockIdx.x * 128;
    float* Co = scores + (size_t)h * SQ * SQ;

    if (blockIdx.x > blockIdx.y) {
        // strictly above diagonal: weights are exactly 0 — write them here
        const float4 z4 = make_float4(0.f, 0.f, 0.f, 0.f);
        const int tid = threadIdx.x;
#pragma unroll
        for (int it = 0; it < 16; it++) {
            int c = tid + it * 256;          // 4096 float4 chunks
            int row = c >> 5;                // 128 rows
            int col = (c & 31) * 4;          // 128 floats
            *(float4*)(Co + (size_t)(q0 + row) * SQ + k0 + col) = z4;
        }
        return;
    }

    extern __shared__ char smem[];
    const uint32_t sb = smem_u32(smem);
    const int tid = threadIdx.x;
    const int w = tid >> 5, l = tid & 31;
    const int wm = w >> 2, wn = w & 3;
    const size_t hb = (size_t)h * SQ * HD;

#pragma unroll
    for (int it = 0; it < 16; it++) {
        int c = tid + it * 256;
        int o = c >> 10;
        int row = (c >> 3) & 127;
        int chk = c & 7;
        const __half* p = (o == 0) ? Qh : (o == 1) ? Ql
                         : (o == 2) ? Kh : Kl;
        int rb = (o < 2) ? q0 : k0;
        const void* g = p + hb + (size_t)(rb + row) * HD + chk * 8;
        uint32_t d = sb + (uint32_t)o * TILE_B + sw(row * 128 + chk * 16);
        asm volatile("cp.async.cg.shared.global [%0], [%1], 16;\n"
                     :: "r"(d), "l"(g));
    }
    asm volatile("cp.async.commit_group;\n" ::: "memory");
    asm volatile("cp.async.wait_group 0;\n" ::: "memory");
    __syncthreads();

    float acc[4][4][4] = {};
    mma_stage<3>(sb, wm, wn, l, acc);

#pragma unroll
    for (int mt = 0; mt < 4; mt++)
#pragma unroll
        for (int nt = 0; nt < 4; nt++) {
            int m = q0 + wm * 64 + mt * 16 + (l >> 2);
            int n = k0 + wn * 32 + nt * 8 + (l & 3) * 2;
#pragma unroll
            for (int hf = 0; hf < 2; hf++) {
                size_t idx = (size_t)(m + hf * 8) * SQ + n;
                Co[idx]     = acc[mt][nt][hf * 2 + 0];
                Co[idx + 1] = acc[mt][nt][hf * 2 + 1];
            }
        }
}

// ============================================================================
// Causal softmax, issue-lean: float4 loads/stores over the causal 128-tile
// span only, warp-shuffle reductions (3 barriers), packed fp16 side writes.
// ============================================================================
__global__ void __launch_bounds__(256)
softmax_causal(float* __restrict__ scores,
               __half* __restrict__ AwH, __half* __restrict__ AwL)
{
    const int q = blockIdx.x;
    const int h = blockIdx.y;
    const int t = threadIdx.x;
    const size_t rbase = ((size_t)h * SQ + q) * SQ;
    float* row = scores + rbase;
    const int kend = ((q >> 7) + 1) << 7;   // causal span (multiple of 128)
    const int nvec = kend >> 2;             // float4 chunks (multiple of 32)

    const float NEG_INF = __int_as_float(0xff800000);
    float4 vv[2];
    float mx = NEG_INF;
#pragma unroll
    for (int it = 0; it < 2; it++) {
        int c = t + it * 256;
        if (c < nvec) {
            float4 f = *(const float4*)(row + c * 4);
            int base = c * 4;
            f.x = (base + 0 <= q) ? f.x : NEG_INF;
            f.y = (base + 1 <= q) ? f.y : NEG_INF;
            f.z = (base + 2 <= q) ? f.z : NEG_INF;
            f.w = (base + 3 <= q) ? f.w : NEG_INF;
            vv[it] = f;
            mx = fmaxf(mx, fmaxf(fmaxf(f.x, f.y), fmaxf(f.z, f.w)));
        } else {
            vv[it] = make_float4(NEG_INF, NEG_INF, NEG_INF, NEG_INF);
        }
    }

    __shared__ float redm[8], reds[8];
#pragma unroll
    for (int o = 16; o; o >>= 1)
        mx = fmaxf(mx, __shfl_xor_sync(0xffffffffu, mx, o));
    if ((t & 31) == 0) redm[t >> 5] = mx;
    __syncthreads();
    if (t < 32) {
        float m = (t < 8) ? redm[t] : NEG_INF;
#pragma unroll
        for (int o = 4; o; o >>= 1)
            m = fmaxf(m, __shfl_xor_sync(0xffffffffu, m, o));
        if (t == 0) redm[0] = m;
    }
    __syncthreads();
    mx = redm[0];

    float sum = 0.0f;
    float4 e[2];
#pragma unroll
    for (int it = 0; it < 2; it++) {
        float4 f = vv[it];
        float e0 = __expf(f.x - mx), e1 = __expf(f.y - mx);
        float e2 = __expf(f.z - mx), e3 = __expf(f.w - mx);
        e[it] = make_float4(e0, e1, e2, e3);
        sum += (e0 + e1) + (e2 + e3);
    }
#pragma unroll
    for (int o = 16; o; o >>= 1)
        sum += __shfl_xor_sync(0xffffffffu, sum, o);
    if ((t & 31) == 0) reds[t >> 5] = sum;
    __syncthreads();
    if (t < 32) {
        float s = (t < 8) ? reds[t] : 0.0f;
#pragma unroll
        for (int o = 4; o; o >>= 1)
            s += __shfl_xor_sync(0xffffffffu, s, o);
        if (t == 0) reds[0] = s;
    }
    __syncthreads();
    const float inv = 1.0f / reds[0];

#pragma unroll
    for (int it = 0; it < 2; it++) {
        int c = t + it * 256;
        if (c >= nvec) continue;
        float w0 = e[it].x * inv, w1 = e[it].y * inv;
        float w2 = e[it].z * inv, w3 = e[it].w * inv;
        *(float4*)(row + c * 4) = make_float4(w0, w1, w2, w3);
        __half h0 = __float2half_rn(w0), h1 = __float2half_rn(w1);
        __half h2 = __float2half_rn(w2), h3 = __float2half_rn(w3);
        __half l0 = __float2half_rn(w0 - __half2float(h0));
        __half l1 = __float2half_rn(w1 - __half2float(h1));
        __half l2 = __float2half_rn(w2 - __half2float(h2));
        __half l3 = __float2half_rn(w3 - __half2float(h3));
        __half hp[4] = {h0, h1, h2, h3};
        __half lp[4] = {l0, l1, l2, l3};
        *(uint2*)(AwH + rbase + c * 4) = *(const uint2*)hp;
        *(uint2*)(AwL + rbase + c * 4) = *(const uint2*)lp;
    }
}

// ============================================================================
// Tensor-core attn_v: ctx = W @ V (split fp16, 3-product). Epilogue writes
// ctx directly as fp16 hi/lo in [s][e] layout (feeds 2-product out-proj).
// ============================================================================
#define AV_WH 0
#define AV_WL 32768
#define AV_VH 65536
#define AV_VL 81920
#define AV_BUF 98304
#define AV_SMEM (2 * AV_BUF)

__global__ void __launch_bounds__(256)
attn_v_mma(const __half* __restrict__ AwH, const __half* __restrict__ AwL,
           const __half* __restrict__ VsH, const __half* __restrict__ VsL,
           __half* __restrict__ ctxH, __half* __restrict__ ctxL)
{
    extern __shared__ char smem[];
    const uint32_t sb = smem_u32(smem);
    const int tid = threadIdx.x;
    const int w = tid >> 5, l = tid & 31;
    const int wm = w >> 2, wn = w & 3;
    const int h  = blockIdx.y;
    const int qt = 15 - blockIdx.x;
    const int q0 = qt * 128;
    const size_t wb = ((size_t)h * SQ + q0) * SQ;
    const size_t vb = (size_t)h * SQ * HD;

    auto issue = [&](int s, int k0) {
        const uint32_t bufb = sb + (uint32_t)s * AV_BUF;
#pragma unroll
        for (int it = 0; it < 16; it++) {
            int c = tid + it * 256;
            int op = c >> 11;
            int cc = c & 2047;
            int row = cc >> 4;
            int ch  = cc & 15;
            const __half* p = op ? AwL : AwH;
            const void* g = p + wb + (size_t)row * SQ + k0 + ch * 8;
            uint32_t d = bufb + (op ? AV_WL : AV_WH) + (uint32_t)(ch >> 3) * 16384
                         + sw(row * 128 + (ch & 7) * 16);
            asm volatile("cp.async.cg.shared.global [%0], [%1], 16;\n"
                         :: "r"(d), "l"(g));
        }
#pragma unroll
        for (int it = 0; it < 8; it++) {
            int c = tid + it * 256;
            int op = c >> 10;
            int cc = c & 1023;
            int row = cc >> 3;
            int ch  = cc & 7;
            const __half* p = op ? VsL : VsH;
            const void* g = p + vb + (size_t)(k0 + row) * HD + ch * 8;
            uint32_t d = bufb + (op ? AV_VL : AV_VH) + sw(row * 128 + ch * 16);
            asm volatile("cp.async.cg.shared.global [%0], [%1], 16;\n"
                         :: "r"(d), "l"(g));
        }
        asm volatile("cp.async.commit_group;\n" ::: "memory");
    };

    float acc[4][2][4] = {};
    const int NT = qt + 1;
    issue(0, 0);

    for (int i = 0; i < NT; i++) {
        if (i + 1 < NT) {
            issue((i + 1) & 1, (i + 1) * 128);
            asm volatile("cp.async.wait_group 1;\n" ::: "memory");
        } else {
            asm volatile("cp.async.wait_group 0;\n" ::: "memory");
        }
        __syncthreads();

        const uint32_t bufb = sb + (uint32_t)(i & 1) * AV_BUF;
#pragma unroll
        for (int ks = 0; ks < 8; ks++) {
            int half_ = ks >> 2, ksl = ks & 3;
            uint32_t ah[4][4], al[4][4];
#pragma unroll
            for (int mt = 0; mt < 4; mt++) {
                int rowq = wm * 64 + mt * 16 + (l & 15);
                int chk = ksl * 2 + (l >> 4);
                uint32_t off = sw(rowq * 128 + chk * 16);
                ldsm4(ah[mt], bufb + AV_WH + half_ * 16384 + off);
                ldsm4(al[mt], bufb + AV_WL + half_ * 16384 + off);
            }
            uint32_t bh[4], bl[4];
            {
                int rowk = ks * 16 + (l & 15);
                int colb = wn * 32 + (l >> 4) * 16;
                uint32_t off = sw(rowk * 128 + colb);
                ldsm4t(bh, bufb + AV_VH + off);
                ldsm4t(bl, bufb + AV_VL + off);
            }
#pragma unroll
            for (int mt = 0; mt < 4; mt++)
#pragma unroll
                for (int nt = 0; nt < 2; nt++) {
                    mma16816(acc[mt][nt], ah[mt], bh + 2 * nt);
                    mma16816(acc[mt][nt], ah[mt], bl + 2 * nt);
                    mma16816(acc[mt][nt], al[mt], bh + 2 * nt);
                }
        }
        __syncthreads();
    }

#pragma unroll
    for (int mt = 0; mt < 4; mt++)
#pragma unroll
        for (int nt = 0; nt < 2; nt++)
#pragma unroll
            for (int hf = 0; hf < 2; hf++) {
                int q = q0 + wm * 64 + mt * 16 + (l >> 2) + hf * 8;
                int d = wn * 16 + nt * 8 + (l & 3) * 2;
                float v0 = acc[mt][nt][hf * 2 + 0];
                float v1 = acc[mt][nt][hf * 2 + 1];
                __half h0 = __float2half_rn(v0);
                __half h1 = __float2half_rn(v1);
                __half l0 = __float2half_rn(v0 - __half2float(h0));
                __half l1 = __float2half_rn(v1 - __half2float(h1));
                size_t idx = (size_t)q * EM + h * HD + d;
                __half2 hp; hp.x = h0; hp.y = h1;
                __half2 lp; lp.x = l0; lp.y = l1;
                *(__half2*)(ctxH + idx) = hp;
                *(__half2*)(ctxL + idx) = lp;
            }
}

// ============================================================================
extern "C" void kernel_launch(void* const* d_in, const int* in_sizes, int n_in,
                              void* d_out, int out_size)
{
    const float* hid = (const float*)d_in[0];
    const float* Wq = (const float*)d_in[2];
    const float* bq = (const float*)d_in[3];
    const float* Wk = (const float*)d_in[4];
    const float* bk = (const float*)d_in[5];
    const float* Wv = (const float*)d_in[6];
    const float* bv = (const float*)d_in[7];
    const float* Wo = (const float*)d_in[8];
    const float* bo = (const float*)d_in[9];
    float* out = (float*)d_out;

    float *gq, *gk, *gv, *gsc;
    cudaGetSymbolAddress((void**)&gq,  g_Q);
    cudaGetSymbolAddress((void**)&gk,  g_K);
    cudaGetSymbolAddress((void**)&gv,  g_V);
    cudaGetSymbolAddress((void**)&gsc, g_scores);

    __half *hH, *hL, *qH, *qL, *kH, *kL, *vH, *vL, *oH, *oL, *cH, *cL;
    __half *QsH, *QsL, *KsH, *KsL, *VsH, *VsL, *AwH, *AwL;
    cudaGetSymbolAddress((void**)&hH, g_hidH); cudaGetSymbolAddress((void**)&hL, g_hidL);
    cudaGetSymbolAddress((void**)&qH, g_WqH);  cudaGetSymbolAddress((void**)&qL, g_WqL);
    cudaGetSymbolAddress((void**)&kH, g_WkH);  cudaGetSymbolAddress((void**)&kL, g_WkL);
    cudaGetSymbolAddress((void**)&vH, g_WvH);  cudaGetSymbolAddress((void**)&vL, g_WvL);
    cudaGetSymbolAddress((void**)&oH, g_WoH);  cudaGetSymbolAddress((void**)&oL, g_WoL);
    cudaGetSymbolAddress((void**)&cH, g_ctxH); cudaGetSymbolAddress((void**)&cL, g_ctxL);
    cudaGetSymbolAddress((void**)&QsH, g_QsH); cudaGetSymbolAddress((void**)&QsL, g_QsL);
    cudaGetSymbolAddress((void**)&KsH, g_KsH); cudaGetSymbolAddress((void**)&KsL, g_KsL);
    cudaGetSymbolAddress((void**)&VsH, g_VsH); cudaGetSymbolAddress((void**)&VsL, g_VsL);
    cudaGetSymbolAddress((void**)&AwH, g_AwH); cudaGetSymbolAddress((void**)&AwL, g_AwL);

    cudaFuncSetAttribute(qkv_gemm, cudaFuncAttributeMaxDynamicSharedMemorySize, SMEM_SZ);
    cudaFuncSetAttribute(out_gemm, cudaFuncAttributeMaxDynamicSharedMemorySize, SMEM_SZ);
    cudaFuncSetAttribute(scores_mma, cudaFuncAttributeMaxDynamicSharedMemorySize, SC_SMEM);
    cudaFuncSetAttribute(attn_v_mma, cudaFuncAttributeMaxDynamicSharedMemorySize, AV_SMEM);

    const size_t n_attn = (size_t)SQ * EM;
    const size_t n_w    = (size_t)NH * SQ * SQ;
    const size_t n_kv   = (size_t)NH * SQ * HD;
    const bool has_w  = (size_t)out_size >= n_attn + n_w;
    const bool has_kv = (size_t)out_size >= n_attn + n_w + 2 * n_kv;
    float* scores = has_w ? (out + n_attn) : gsc;

    const int NCV = SQ * EM;
    split_f16_all<<<dim3(2048, 5), 256>>>(hid, Wq, Wk, Wv, Wo,
                                          hH, hL, qH, qL, kH, kL,
                                          vH, vL, oH, oL, NCV);

    dim3 blk(256);
    qkv_gemm<<<dim3(16, 16, 3), blk, SMEM_SZ>>>(
        hH, hL, qH, qL, kH, kL, vH, bq, bk, bv,
        gq, gk, gv, QsH, QsL, KsH, KsL, VsH, VsL);

    scores_mma<<<dim3(16, 16, NH), blk, SC_SMEM>>>(QsH, QsL, KsH, KsL, scores);
    softmax_causal<<<dim3(SQ, NH), blk>>>(scores, AwH, AwL);
    attn_v_mma<<<dim3(16, NH), blk, AV_SMEM>>>(AwH, AwL, VsH, VsL, cH, cL);

    out_gemm<<<dim3(16, 16), blk, SMEM_SZ>>>(cH, cL, oH, bo, out);

    if (has_kv) {
        cudaMemcpyAsync(out + n_attn + n_w, gk, n_kv * sizeof(float),
                        cudaMemcpyDeviceToDevice);
        cudaMemcpyAsync(out + n_attn + n_w + n_kv, gv, n_kv * sizeof(float),
                        cudaMemcpyDeviceToDevice);
    }
}

// round 15
// speedup vs baseline: 1.0709x; 1.0709x over previous
#include <cuda_runtime.h>
#include <cuda_fp16.h>
#include <cstdint>

#define SQ 2048
#define EM 2048
#define NH 32
#define HD 64

// ---------------- device scratch (allocation-free rule) ----------------------
__device__ float g_scores[(size_t)NH * SQ * SQ];   // fallback only

__device__ __half g_hidH[SQ * EM], g_hidL[SQ * EM];
__device__ __half g_WqH[EM * EM],  g_WqL[EM * EM];
__device__ __half g_WkH[EM * EM],  g_WkL[EM * EM];
__device__ __half g_WvH[EM * EM],  g_WvL[EM * EM];
__device__ __half g_WoH[EM * EM],  g_WoL[EM * EM];
__device__ __half g_ctxH[SQ * EM], g_ctxL[SQ * EM];
// shaped [h][s][hd] hi/lo splits written by projection epilogues
__device__ __half g_QsH[NH * SQ * HD], g_QsL[NH * SQ * HD];
__device__ __half g_KsH[NH * SQ * HD], g_KsL[NH * SQ * HD];
__device__ __half g_VsH[NH * SQ * HD], g_VsL[NH * SQ * HD];
// fp16 (hi only) of normalized attention weights (causal 128-tiles only)
__device__ __half g_AwH[(size_t)NH * SQ * SQ];

// ---------------- helpers ----------------------------------------------------
__device__ __forceinline__ uint32_t smem_u32(const void* p) {
    uint32_t a;
    asm("{ .reg .u64 t; cvta.to.shared.u64 t, %1; cvt.u32.u64 %0, t; }"
        : "=r"(a) : "l"(p));
    return a;
}
__device__ __forceinline__ void ldsm4(uint32_t* r, uint32_t addr) {
    asm volatile("ldmatrix.sync.aligned.m8n8.x4.shared.b16 {%0,%1,%2,%3}, [%4];"
                 : "=r"(r[0]), "=r"(r[1]), "=r"(r[2]), "=r"(r[3]) : "r"(addr));
}
__device__ __forceinline__ void ldsm4t(uint32_t* r, uint32_t addr) {
    asm volatile("ldmatrix.sync.aligned.m8n8.x4.trans.shared.b16 {%0,%1,%2,%3}, [%4];"
                 : "=r"(r[0]), "=r"(r[1]), "=r"(r[2]), "=r"(r[3]) : "r"(addr));
}
__device__ __forceinline__ void mma16816(float* c, const uint32_t* a,
                                         const uint32_t* b) {
    asm volatile(
        "mma.sync.aligned.m16n8k16.row.col.f32.f16.f16.f32 "
        "{%0,%1,%2,%3}, {%4,%5,%6,%7}, {%8,%9}, {%0,%1,%2,%3};"
        : "+f"(c[0]), "+f"(c[1]), "+f"(c[2]), "+f"(c[3])
        : "r"(a[0]), "r"(a[1]), "r"(a[2]), "r"(a[3]), "r"(b[0]), "r"(b[1]));
}
__device__ __forceinline__ uint32_t sw(uint32_t off) {
    return off ^ ((off >> 3) & 0x70);
}

// fp32 -> fp16 hi/lo split for all 5 matrices in ONE launch (grid.y selects)
__global__ void __launch_bounds__(256)
split_f16_all(const float* __restrict__ x0, const float* __restrict__ x1,
              const float* __restrict__ x2, const float* __restrict__ x3,
              const float* __restrict__ x4,
              __half* __restrict__ h0, __half* __restrict__ l0,
              __half* __restrict__ h1, __half* __restrict__ l1,
              __half* __restrict__ h2, __half* __restrict__ l2,
              __half* __restrict__ h3, __half* __restrict__ l3,
              __half* __restrict__ h4, __half* __restrict__ l4, int n)
{
    const int z = blockIdx.y;
    const float* x = (z == 0) ? x0 : (z == 1) ? x1 : (z == 2) ? x2
                   : (z == 3) ? x3 : x4;
    __half* hi = (z == 0) ? h0 : (z == 1) ? h1 : (z == 2) ? h2
               : (z == 3) ? h3 : h4;
    __half* lo = (z == 0) ? l0 : (z == 1) ? l1 : (z == 2) ? l2
               : (z == 3) ? l3 : l4;
    const int stride = gridDim.x * 256 * 4;
    for (int i = (blockIdx.x * 256 + threadIdx.x) * 4; i < n; i += stride) {
        float4 v = *(const float4*)(x + i);
        __half h[4], l[4];
        float vv[4] = {v.x, v.y, v.z, v.w};
#pragma unroll
        for (int j = 0; j < 4; j++) {
            h[j] = __float2half_rn(vv[j]);
            l[j] = __float2half_rn(vv[j] - __half2float(h[j]));
        }
        *(uint2*)(hi + i) = *(const uint2*)h;
        *(uint2*)(lo + i) = *(const uint2*)l;
    }
}

// ============================================================================
// MMA stage over operand tiles (Ah,Al,Bh[,Bl]), 128 rows x 128B each.
// NPROD==3: AhBh + AhBl + AlBh.  NPROD==2: AhBh + AlBh (Bl never touched).
// ============================================================================
#define TILE_B 16384

template <int NPROD>
__device__ __forceinline__ void
mma_stage(uint32_t base, int wm, int wn, int l, float acc[4][4][4])
{
    const uint32_t aH = base, aL = base + TILE_B;
    const uint32_t bH = base + 2 * TILE_B, bL = base + 3 * TILE_B;
#pragma unroll
    for (int ks = 0; ks < 4; ks++) {
        uint32_t ah[4][4], al[4][4], bh[4][2], bl[4][2];
#pragma unroll
        for (int mt = 0; mt < 4; mt++) {
            int row = wm * 64 + mt * 16 + (l & 15);
            int chk = ks * 2 + (l >> 4);
            uint32_t off = sw(row * 128 + chk * 16);
            ldsm4(ah[mt], aH + off);
            ldsm4(al[mt], aL + off);
        }
#pragma unroll
        for (int j = 0; j < 2; j++) {
            int row = wn * 32 + j * 16 + (l & 7) + ((l >> 4) << 3);
            int chk = ks * 2 + ((l >> 3) & 1);
            uint32_t off = sw(row * 128 + chk * 16);
            uint32_t t4[4];
            ldsm4(t4, bH + off);
            bh[2 * j][0] = t4[0]; bh[2 * j][1] = t4[1];
            bh[2 * j + 1][0] = t4[2]; bh[2 * j + 1][1] = t4[3];
            if (NPROD == 3) {
                ldsm4(t4, bL + off);
                bl[2 * j][0] = t4[0]; bl[2 * j][1] = t4[1];
                bl[2 * j + 1][0] = t4[2]; bl[2 * j + 1][1] = t4[3];
            }
        }
#pragma unroll
        for (int mt = 0; mt < 4; mt++)
#pragma unroll
            for (int nt = 0; nt < 4; nt++) {
                mma16816(acc[mt][nt], ah[mt], bh[nt]);
                if (NPROD == 3) mma16816(acc[mt][nt], ah[mt], bl[nt]);
                mma16816(acc[mt][nt], al[mt], bh[nt]);
            }
    }
}

// ============================================================================
// GEMM body (2-stage ring): C = (A@B^T + bias)*scale, K=2048.
// C may be nullptr (skip fp32 write; fp16 split still written if SPLIT).
// ============================================================================
#define SMEM_SZ (8 * TILE_B)

template <int NPROD, int MODE, bool SPLIT>
__device__ __forceinline__ void
gemm_body(const __half* Ah, const __half* Al,
          const __half* Bh, const __half* Bl,
          const float* bias, float* C, __half* Chi, __half* Clo,
          float scale, int m0, int n0, uint32_t sb, int tid)
{
    const int w = tid >> 5, l = tid & 31;
    const int wm = w >> 2, wn = w & 3;

    auto issue = [&](int s, int k0) {
#pragma unroll
        for (int it = 0; it < 16; it++) {
            if (NPROD == 2 && it >= 12) continue;   // skip Bl tile
            int c = tid + it * 256;
            int o = c >> 10;
            int row = (c >> 3) & 127;
            int chk = c & 7;
            const __half* p = (o == 0) ? Ah : (o == 1) ? Al
                             : (o == 2) ? Bh : Bl;
            int rb = (o < 2) ? m0 : n0;
            const void* g = p + (size_t)(rb + row) * 2048 + k0 + chk * 8;
            uint32_t d = sb + (uint32_t)(s * 4 + o) * TILE_B
                         + sw(row * 128 + chk * 16);
            asm volatile("cp.async.cg.shared.global [%0], [%1], 16;\n"
                         :: "r"(d), "l"(g));
        }
        asm volatile("cp.async.commit_group;\n" ::: "memory");
    };

    float acc[4][4][4] = {};
    issue(0, 0);

    const int NS = 2048 / 64;
    for (int i = 0; i < NS; i++) {
        if (i + 1 < NS) {
            issue((i + 1) & 1, (i + 1) * 64);
            asm volatile("cp.async.wait_group 1;\n" ::: "memory");
        } else {
            asm volatile("cp.async.wait_group 0;\n" ::: "memory");
        }
        __syncthreads();
        mma_stage<NPROD>(sb + (uint32_t)((i & 1) * 4) * TILE_B, wm, wn, l, acc);
        __syncthreads();
    }

#pragma unroll
    for (int mt = 0; mt < 4; mt++) {
#pragma unroll
        for (int nt = 0; nt < 4; nt++) {
            int m = m0 + wm * 64 + mt * 16 + (l >> 2);
            int n = n0 + wn * 32 + nt * 8 + (l & 3) * 2;
#pragma unroll
            for (int hf = 0; hf < 2; hf++) {
                int row = m + hf * 8;
                float v0 = (acc[mt][nt][hf * 2 + 0] + bias[n]) * scale;
                float v1 = (acc[mt][nt][hf * 2 + 1] + bias[n + 1]) * scale;
                size_t idx;
                if (MODE == 0)
                    idx = (size_t)row * 2048 + n;
                else
                    idx = (((size_t)(n >> 6)) * SQ + row) * HD + (n & 63);
                if (C) {
                    C[idx] = v0;
                    C[idx + 1] = v1;
                }
                if (SPLIT) {
                    __half h0 = __float2half_rn(v0);
                    __half h1 = __float2half_rn(v1);
                    __half l0 = __float2half_rn(v0 - __half2float(h0));
                    __half l1 = __float2half_rn(v1 - __half2float(h1));
                    Chi[idx] = h0; Chi[idx + 1] = h1;
                    Clo[idx] = l0; Clo[idx + 1] = l1;
                }
            }
        }
    }
}

// Merged Q/K/V projection, grid (16,16,3); compile-time dispatch per z.
// Q writes no fp32 (unused); K/V fp32 go straight into the output buffer.
__global__ void __launch_bounds__(256)
qkv_gemm(const __half* __restrict__ hH, const __half* __restrict__ hL,
         const __half* __restrict__ WqH, const __half* __restrict__ WqL,
         const __half* __restrict__ WkH, const __half* __restrict__ WkL,
         const __half* __restrict__ WvH,
         const float* __restrict__ bq, const float* __restrict__ bk,
         const float* __restrict__ bv,
         float* __restrict__ Ck, float* __restrict__ Cv,
         __half* __restrict__ QsH, __half* __restrict__ QsL,
         __half* __restrict__ KsH, __half* __restrict__ KsL,
         __half* __restrict__ VsH, __half* __restrict__ VsL)
{
    extern __shared__ char smem[];
    const uint32_t sb = smem_u32(smem);
    const int tid = threadIdx.x;
    const int m0 = blockIdx.y * 128, n0 = blockIdx.x * 128;
    const int z = blockIdx.z;
    if (z == 0)
        gemm_body<3, 1, true>(hH, hL, WqH, WqL, bq, nullptr, QsH, QsL,
                              0.125f, m0, n0, sb, tid);
    else if (z == 1)
        gemm_body<3, 1, true>(hH, hL, WkH, WkL, bk, Ck, KsH, KsL,
                              1.0f, m0, n0, sb, tid);
    else
        gemm_body<2, 1, true>(hH, hL, WvH, WvH, bv, Cv, VsH, VsL,
                              1.0f, m0, n0, sb, tid);
}

// Out-projection: 2-product, plain row-major output.
__global__ void __launch_bounds__(256)
out_gemm(const __half* __restrict__ cH, const __half* __restrict__ cL,
         const __half* __restrict__ WoH,
         const float* __restrict__ bo, float* __restrict__ out)
{
    extern __shared__ char smem[];
    gemm_body<2, 0, false>(cH, cL, WoH, WoH, bo, out, nullptr, nullptr, 1.0f,
                           blockIdx.y * 128, blockIdx.x * 128,
                           smem_u32(smem), threadIdx.x);
}

// ============================================================================
// Tensor-core scores: scores[h] = Qs @ Ks^T per head, K=64 (one stage).
// Above-diagonal tiles: pure zero-fill (these are the final weight zeros).
// ============================================================================
#define SC_SMEM (4 * TILE_B)

__global__ void __launch_bounds__(256)
scores_mma(const __half* __restrict__ Qh, const __half* __restrict__ Ql,
           const __half* __restrict__ Kh, const __half* __restrict__ Kl,
           float* __restrict__ scores)
{
    const int h  = blockIdx.z;
    const int q0 = blockIdx.y * 128;
    const int k0 = blockIdx.x * 128;
    float* Co = scores + (size_t)h * SQ * SQ;

    if (blockIdx.x > blockIdx.y) {
        const float4 z4 = make_float4(0.f, 0.f, 0.f, 0.f);
        const int tid = threadIdx.x;
#pragma unroll
        for (int it = 0; it < 16; it++) {
            int c = tid + it * 256;
            int row = c >> 5;
            int col = (c & 31) * 4;
            *(float4*)(Co + (size_t)(q0 + row) * SQ + k0 + col) = z4;
        }
        return;
    }

    extern __shared__ char smem[];
    const uint32_t sb = smem_u32(smem);
    const int tid = threadIdx.x;
    const int w = tid >> 5, l = tid & 31;
    const int wm = w >> 2, wn = w & 3;
    const size_t hb = (size_t)h * SQ * HD;

#pragma unroll
    for (int it = 0; it < 16; it++) {
        int c = tid + it * 256;
        int o = c >> 10;
        int row = (c >> 3) & 127;
        int chk = c & 7;
        const __half* p = (o == 0) ? Qh : (o == 1) ? Ql
                         : (o == 2) ? Kh : Kl;
        int rb = (o < 2) ? q0 : k0;
        const void* g = p + hb + (size_t)(rb + row) * HD + chk * 8;
        uint32_t d = sb + (uint32_t)o * TILE_B + sw(row * 128 + chk * 16);
        asm volatile("cp.async.cg.shared.global [%0], [%1], 16;\n"
                     :: "r"(d), "l"(g));
    }
    asm volatile("cp.async.commit_group;\n" ::: "memory");
    asm volatile("cp.async.wait_group 0;\n" ::: "memory");
    __syncthreads();

    float acc[4][4][4] = {};
    mma_stage<3>(sb, wm, wn, l, acc);

#pragma unroll
    for (int mt = 0; mt < 4; mt++)
#pragma unroll
        for (int nt = 0; nt < 4; nt++) {
            int m = q0 + wm * 64 + mt * 16 + (l >> 2);
            int n = k0 + wn * 32 + nt * 8 + (l & 3) * 2;
#pragma unroll
            for (int hf = 0; hf < 2; hf++) {
                size_t idx = (size_t)(m + hf * 8) * SQ + n;
                Co[idx]     = acc[mt][nt][hf * 2 + 0];
                Co[idx + 1] = acc[mt][nt][hf * 2 + 1];
            }
        }
}

// ============================================================================
// Causal softmax: float4 over causal span, warp-shuffle reductions,
// packed fp16 (hi only) side write.
// ============================================================================
__global__ void __launch_bounds__(256)
softmax_causal(float* __restrict__ scores, __half* __restrict__ AwH)
{
    const int q = blockIdx.x;
    const int h = blockIdx.y;
    const int t = threadIdx.x;
    const size_t rbase = ((size_t)h * SQ + q) * SQ;
    float* row = scores + rbase;
    const int kend = ((q >> 7) + 1) << 7;
    const int nvec = kend >> 2;

    const float NEG_INF = __int_as_float(0xff800000);
    float4 vv[2];
    float mx = NEG_INF;
#pragma unroll
    for (int it = 0; it < 2; it++) {
        int c = t + it * 256;
        if (c < nvec) {
            float4 f = *(const float4*)(row + c * 4);
            int base = c * 4;
            f.x = (base + 0 <= q) ? f.x : NEG_INF;
            f.y = (base + 1 <= q) ? f.y : NEG_INF;
            f.z = (base + 2 <= q) ? f.z : NEG_INF;
            f.w = (base + 3 <= q) ? f.w : NEG_INF;
            vv[it] = f;
            mx = fmaxf(mx, fmaxf(fmaxf(f.x, f.y), fmaxf(f.z, f.w)));
        } else {
            vv[it] = make_float4(NEG_INF, NEG_INF, NEG_INF, NEG_INF);
        }
    }

    __shared__ float redm[8], reds[8];
#pragma unroll
    for (int o = 16; o; o >>= 1)
        mx = fmaxf(mx, __shfl_xor_sync(0xffffffffu, mx, o));
    if ((t & 31) == 0) redm[t >> 5] = mx;
    __syncthreads();
    if (t < 32) {
        float m = (t < 8) ? redm[t] : NEG_INF;
#pragma unroll
        for (int o = 4; o; o >>= 1)
            m = fmaxf(m, __shfl_xor_sync(0xffffffffu, m, o));
        if (t == 0) redm[0] = m;
    }
    __syncthreads();
    mx = redm[0];

    float sum = 0.0f;
    float4 e[2];
#pragma unroll
    for (int it = 0; it < 2; it++) {
        float4 f = vv[it];
        float e0 = __expf(f.x - mx), e1 = __expf(f.y - mx);
        float e2 = __expf(f.z - mx), e3 = __expf(f.w - mx);
        e[it] = make_float4(e0, e1, e2, e3);
        sum += (e0 + e1) + (e2 + e3);
    }
#pragma unroll
    for (int o = 16; o; o >>= 1)
        sum += __shfl_xor_sync(0xffffffffu, sum, o);
    if ((t & 31) == 0) reds[t >> 5] = sum;
    __syncthreads();
    if (t < 32) {
        float s = (t < 8) ? reds[t] : 0.0f;
#pragma unroll
        for (int o = 4; o; o >>= 1)
            s += __shfl_xor_sync(0xffffffffu, s, o);
        if (t == 0) reds[0] = s;
    }
    __syncthreads();
    const float inv = 1.0f / reds[0];

#pragma unroll
    for (int it = 0; it < 2; it++) {
        int c = t + it * 256;
        if (c >= nvec) continue;
        float w0 = e[it].x * inv, w1 = e[it].y * inv;
        float w2 = e[it].z * inv, w3 = e[it].w * inv;
        *(float4*)(row + c * 4) = make_float4(w0, w1, w2, w3);
        __half h0 = __float2half_rn(w0), h1 = __float2half_rn(w1);
        __half h2 = __float2half_rn(w2), h3 = __float2half_rn(w3);
        __half hp[4] = {h0, h1, h2, h3};
        *(uint2*)(AwH + rbase + c * 4) = *(const uint2*)hp;
    }
}

// ============================================================================
// Tensor-core attn_v: ctx = W @ V, W rounded to fp16 (hi only), V split.
// Products: Wh·Vh + Wh·Vl.  Epilogue writes ctx as fp16 hi/lo in [s][e].
// Smem per buf: WH[2][128][64] (32KB) + VH (16KB) + VL (16KB) = 64KB.
// ============================================================================
#define AV_WH 0
#define AV_VH 32768
#define AV_VL 49152
#define AV_BUF 65536
#define AV_SMEM (2 * AV_BUF)   // 131072

__global__ void __launch_bounds__(256)
attn_v_mma(const __half* __restrict__ AwH,
           const __half* __restrict__ VsH, const __half* __restrict__ VsL,
           __half* __restrict__ ctxH, __half* __restrict__ ctxL)
{
    extern __shared__ char smem[];
    const uint32_t sb = smem_u32(smem);
    const int tid = threadIdx.x;
    const int w = tid >> 5, l = tid & 31;
    const int wm = w >> 2, wn = w & 3;
    const int h  = blockIdx.y;
    const int qt = 15 - blockIdx.x;
    const int q0 = qt * 128;
    const size_t wb = ((size_t)h * SQ + q0) * SQ;
    const size_t vb = (size_t)h * SQ * HD;

    auto issue = [&](int s, int k0) {
        const uint32_t bufb = sb + (uint32_t)s * AV_BUF;
        // WH: 128 rows x 16 chunks(16B) = 2048 chunks
#pragma unroll
        for (int it = 0; it < 8; it++) {
            int c = tid + it * 256;
            int row = c >> 4;
            int ch  = c & 15;
            const void* g = AwH + wb + (size_t)row * SQ + k0 + ch * 8;
            uint32_t d = bufb + AV_WH + (uint32_t)(ch >> 3) * 16384
                         + sw(row * 128 + (ch & 7) * 16);
            asm volatile("cp.async.cg.shared.global [%0], [%1], 16;\n"
                         :: "r"(d), "l"(g));
        }
        // VH + VL: 2 x 1024 chunks
#pragma unroll
        for (int it = 0; it < 8; it++) {
            int c = tid + it * 256;
            int op = c >> 10;
            int cc = c & 1023;
            int row = cc >> 3;
            int ch  = cc & 7;
            const __half* p = op ? VsL : VsH;
            const void* g = p + vb + (size_t)(k0 + row) * HD + ch * 8;
            uint32_t d = bufb + (op ? AV_VL : AV_VH) + sw(row * 128 + ch * 16);
            asm volatile("cp.async.cg.shared.global [%0], [%1], 16;\n"
                         :: "r"(d), "l"(g));
        }
        asm volatile("cp.async.commit_group;\n" ::: "memory");
    };

    float acc[4][2][4] = {};
    const int NT = qt + 1;
    issue(0, 0);

    for (int i = 0; i < NT; i++) {
        if (i + 1 < NT) {
            issue((i + 1) & 1, (i + 1) * 128);
            asm volatile("cp.async.wait_group 1;\n" ::: "memory");
        } else {
            asm volatile("cp.async.wait_group 0;\n" ::: "memory");
        }
        __syncthreads();

        const uint32_t bufb = sb + (uint32_t)(i & 1) * AV_BUF;
#pragma unroll
        for (int ks = 0; ks < 8; ks++) {
            int half_ = ks >> 2, ksl = ks & 3;
            uint32_t ah[4][4];
#pragma unroll
            for (int mt = 0; mt < 4; mt++) {
                int rowq = wm * 64 + mt * 16 + (l & 15);
                int chk = ksl * 2 + (l >> 4);
                uint32_t off = sw(rowq * 128 + chk * 16);
                ldsm4(ah[mt], bufb + AV_WH + half_ * 16384 + off);
            }
            uint32_t bh[4], bl[4];
            {
                int rowk = ks * 16 + (l & 15);
                int colb = wn * 32 + (l >> 4) * 16;
                uint32_t off = sw(rowk * 128 + colb);
                ldsm4t(bh, bufb + AV_VH + off);
                ldsm4t(bl, bufb + AV_VL + off);
            }
#pragma unroll
            for (int mt = 0; mt < 4; mt++)
#pragma unroll
                for (int nt = 0; nt < 2; nt++) {
                    mma16816(acc[mt][nt], ah[mt], bh + 2 * nt);
                    mma16816(acc[mt][nt], ah[mt], bl + 2 * nt);
                }
        }
        __syncthreads();
    }

#pragma unroll
    for (int mt = 0; mt < 4; mt++)
#pragma unroll
        for (int nt = 0; nt < 2; nt++)
#pragma unroll
            for (int hf = 0; hf < 2; hf++) {
                int q = q0 + wm * 64 + mt * 16 + (l >> 2) + hf * 8;
                int d = wn * 16 + nt * 8 + (l & 3) * 2;
                float v0 = acc[mt][nt][hf * 2 + 0];
                float v1 = acc[mt][nt][hf * 2 + 1];
                __half h0 = __float2half_rn(v0);
                __half h1 = __float2half_rn(v1);
                __half l0 = __float2half_rn(v0 - __half2float(h0));
                __half l1 = __float2half_rn(v1 - __half2float(h1));
                size_t idx = (size_t)q * EM + h * HD + d;
                __half2 hp; hp.x = h0; hp.y = h1;
                __half2 lp; lp.x = l0; lp.y = l1;
                *(__half2*)(ctxH + idx) = hp;
                *(__half2*)(ctxL + idx) = lp;
            }
}

// ============================================================================
extern "C" void kernel_launch(void* const* d_in, const int* in_sizes, int n_in,
                              void* d_out, int out_size)
{
    const float* hid = (const float*)d_in[0];
    const float* Wq = (const float*)d_in[2];
    const float* bq = (const float*)d_in[3];
    const float* Wk = (const float*)d_in[4];
    const float* bk = (const float*)d_in[5];
    const float* Wv = (const float*)d_in[6];
    const float* bv = (const float*)d_in[7];
    const float* Wo = (const float*)d_in[8];
    const float* bo = (const float*)d_in[9];
    float* out = (float*)d_out;

    float* gsc;
    cudaGetSymbolAddress((void**)&gsc, g_scores);

    __half *hH, *hL, *qH, *qL, *kH, *kL, *vH, *vL, *oH, *oL, *cH, *cL;
    __half *QsH, *QsL, *KsH, *KsL, *VsH, *VsL, *AwH;
    cudaGetSymbolAddress((void**)&hH, g_hidH); cudaGetSymbolAddress((void**)&hL, g_hidL);
    cudaGetSymbolAddress((void**)&qH, g_WqH);  cudaGetSymbolAddress((void**)&qL, g_WqL);
    cudaGetSymbolAddress((void**)&kH, g_WkH);  cudaGetSymbolAddress((void**)&kL, g_WkL);
    cudaGetSymbolAddress((void**)&vH, g_WvH);  cudaGetSymbolAddress((void**)&vL, g_WvL);
    cudaGetSymbolAddress((void**)&oH, g_WoH);  cudaGetSymbolAddress((void**)&oL, g_WoL);
    cudaGetSymbolAddress((void**)&cH, g_ctxH); cudaGetSymbolAddress((void**)&cL, g_ctxL);
    cudaGetSymbolAddress((void**)&QsH, g_QsH); cudaGetSymbolAddress((void**)&QsL, g_QsL);
    cudaGetSymbolAddress((void**)&KsH, g_KsH); cudaGetSymbolAddress((void**)&KsL, g_KsL);
    cudaGetSymbolAddress((void**)&VsH, g_VsH); cudaGetSymbolAddress((void**)&VsL, g_VsL);
    cudaGetSymbolAddress((void**)&AwH, g_AwH);

    cudaFuncSetAttribute(qkv_gemm, cudaFuncAttributeMaxDynamicSharedMemorySize, SMEM_SZ);
    cudaFuncSetAttribute(out_gemm, cudaFuncAttributeMaxDynamicSharedMemorySize, SMEM_SZ);
    cudaFuncSetAttribute(scores_mma, cudaFuncAttributeMaxDynamicSharedMemorySize, SC_SMEM);
    cudaFuncSetAttribute(attn_v_mma, cudaFuncAttributeMaxDynamicSharedMemorySize, AV_SMEM);

    const size_t n_attn = (size_t)SQ * EM;
    const size_t n_w    = (size_t)NH * SQ * SQ;
    const size_t n_kv   = (size_t)NH * SQ * HD;
    const bool has_w  = (size_t)out_size >= n_attn + n_w;
    const bool has_kv = (size_t)out_size >= n_attn + n_w + 2 * n_kv;
    float* scores = has_w ? (out + n_attn) : gsc;
    float* Ck = has_kv ? (out + n_attn + n_w) : nullptr;
    float* Cv = has_kv ? (out + n_attn + n_w + n_kv) : nullptr;

    const int NCV = SQ * EM;
    split_f16_all<<<dim3(2048, 5), 256>>>(hid, Wq, Wk, Wv, Wo,
                                          hH, hL, qH, qL, kH, kL,
                                          vH, vL, oH, oL, NCV);

    dim3 blk(256);
    qkv_gemm<<<dim3(16, 16, 3), blk, SMEM_SZ>>>(
        hH, hL, qH, qL, kH, kL, vH, bq, bk, bv,
        Ck, Cv, QsH, QsL, KsH, KsL, VsH, VsL);

    scores_mma<<<dim3(16, 16, NH), blk, SC_SMEM>>>(QsH, QsL, KsH, KsL, scores);
    softmax_causal<<<dim3(SQ, NH), blk>>>(scores, AwH);
    attn_v_mma<<<dim3(16, NH), blk, AV_SMEM>>>(AwH, VsH, VsL, cH, cL);

    out_gemm<<<dim3(16, 16), blk, SMEM_SZ>>>(cH, cL, oH, bo, out);
}